// round 14
// baseline (speedup 1.0000x reference)
#include <cuda_runtime.h>
#include <cuda_fp16.h>
#include <float.h>
#include <stdint.h>

#define D2 64
#define MAX_TABLE_LEN 8192
#define PREPB 264
#define SCALEB 132
#define ROWS_PER_WARP 8

// Scratch (no allocation allowed in kernel_launch)
__device__ __align__(16) __half g_sxh[MAX_TABLE_LEN * D2];   // pairsum(x), fp16
__device__ __align__(16) __half g_syh[MAX_TABLE_LEN * D2];   // pairsum(y), fp16
__device__ __align__(16) float  g_f2 [MAX_TABLE_LEN * D2];   // pairsum(fixed), fp32
__device__ __align__(16) __half g_thx2[MAX_TABLE_LEN * D2];  // combined x, fp16
__device__ __align__(16) __half g_thy2[MAX_TABLE_LEN * D2];  // combined y, fp16
__device__ float g_pmx[PREPB];
__device__ float g_pmy[PREPB];
__device__ float g_inv2[2];
__device__ unsigned int g_done = 0;  // fence-counter; last block resets to 0

// ---------------------------------------------------------------------------
// K1: single-pass prep. Reads x, y, f ONCE (12.6MB); writes unscaled fp16
// pair-sums + fp32 fixed pair-sum while tracking global max of x and y.
// LAST block to finish (fence-counter, no spin — proven) -> g_inv2.
// 264 blocks x 256 thr, one 2-way-batched pass, loads front-batched.
// ---------------------------------------------------------------------------
__global__ void __launch_bounds__(256)
prep_kernel(const float4* __restrict__ x, const float4* __restrict__ y,
            const float4* __restrict__ f, int n4) {
    const int tid = threadIdx.x;
    const int stride = PREPB * 256;
    const int i0 = blockIdx.x * 256 + tid;
    const int i1 = i0 + stride;
    const bool ok0 = (i0 < n4);
    const bool ok1 = (i1 < n4);

    float4 xa0, ya0, fa0, xa1, ya1, fa1;
    if (ok0) { xa0 = x[i0]; ya0 = y[i0]; fa0 = f[i0]; }
    if (ok1) { xa1 = x[i1]; ya1 = y[i1]; fa1 = f[i1]; }

    float mx = -FLT_MAX, my = -FLT_MAX;
    if (ok0) {
        float2 sx = make_float2(xa0.x + xa0.y, xa0.z + xa0.w);
        float2 sy = make_float2(ya0.x + ya0.y, ya0.z + ya0.w);
        ((__half2*)g_sxh)[i0] = __float22half2_rn(sx);
        ((__half2*)g_syh)[i0] = __float22half2_rn(sy);
        ((float2*)g_f2)[i0] = make_float2(fa0.x + fa0.y, fa0.z + fa0.w);
        mx = fmaxf(mx, fmaxf(fmaxf(xa0.x, xa0.y), fmaxf(xa0.z, xa0.w)));
        my = fmaxf(my, fmaxf(fmaxf(ya0.x, ya0.y), fmaxf(ya0.z, ya0.w)));
    }
    if (ok1) {
        float2 sx = make_float2(xa1.x + xa1.y, xa1.z + xa1.w);
        float2 sy = make_float2(ya1.x + ya1.y, ya1.z + ya1.w);
        ((__half2*)g_sxh)[i1] = __float22half2_rn(sx);
        ((__half2*)g_syh)[i1] = __float22half2_rn(sy);
        ((float2*)g_f2)[i1] = make_float2(fa1.x + fa1.y, fa1.z + fa1.w);
        mx = fmaxf(mx, fmaxf(fmaxf(xa1.x, xa1.y), fmaxf(xa1.z, xa1.w)));
        my = fmaxf(my, fmaxf(fmaxf(ya1.x, ya1.y), fmaxf(ya1.z, ya1.w)));
    }

#pragma unroll
    for (int o = 16; o > 0; o >>= 1) {
        mx = fmaxf(mx, __shfl_xor_sync(0xFFFFFFFFu, mx, o));
        my = fmaxf(my, __shfl_xor_sync(0xFFFFFFFFu, my, o));
    }
    __shared__ float smx[8], smy[8];
    __shared__ bool s_last;
    int w = tid >> 5, l = tid & 31;
    if (l == 0) { smx[w] = mx; smy[w] = my; }
    __syncthreads();
    if (tid == 0) {
        for (int i = 1; i < 8; i++) {
            mx = fmaxf(mx, smx[i]);
            my = fmaxf(my, smy[i]);
        }
        g_pmx[blockIdx.x] = mx;
        g_pmy[blockIdx.x] = my;
        __threadfence();
        unsigned int prev = atomicAdd(&g_done, 1u);
        s_last = (prev == PREPB - 1);
    }
    __syncthreads();

    if (s_last && tid < 32) {
        float fx = -FLT_MAX, fy = -FLT_MAX;
        for (int i = tid; i < PREPB; i += 32) {
            fx = fmaxf(fx, g_pmx[i]);
            fy = fmaxf(fy, g_pmy[i]);
        }
#pragma unroll
        for (int o = 16; o > 0; o >>= 1) {
            fx = fmaxf(fx, __shfl_xor_sync(0xFFFFFFFFu, fx, o));
            fy = fmaxf(fy, __shfl_xor_sync(0xFFFFFFFFu, fy, o));
        }
        if (tid == 0) {
            g_inv2[0] = 0.1f / fx;
            g_inv2[1] = 0.1f / fy;
            g_done = 0;  // reset for next graph replay
        }
    }
}

// ---------------------------------------------------------------------------
// K2: scale+combine. combined = fp16(s * inv + f2). Reads 2.1MB, writes 1MB,
// everything L2-hot from K1. 132 blocks x 256 thr, 4-way batched.
// Per index i (half2 granularity): sxh 4B + syh 4B + f2 8B -> 2 x 4B out.
// ---------------------------------------------------------------------------
__global__ void __launch_bounds__(256)
scale_kernel(int n4) {
    const int stride = SCALEB * 256;
    const float invx = g_inv2[0];
    const float invy = g_inv2[1];
    int base = blockIdx.x * 256 + threadIdx.x;

    unsigned int sx[4], sy[4];
    float2 f2v[4];
#pragma unroll
    for (int k = 0; k < 4; k++) {
        int i = base + k * stride;
        if (i < n4) {
            sx[k]  = ((const unsigned int*)g_sxh)[i];
            sy[k]  = ((const unsigned int*)g_syh)[i];
            f2v[k] = ((const float2*)g_f2)[i];
        }
    }
#pragma unroll
    for (int k = 0; k < 4; k++) {
        int i = base + k * stride;
        if (i < n4) {
            float2 xs = __half22float2(*(const __half2*)&sx[k]);
            float2 ys = __half22float2(*(const __half2*)&sy[k]);
            float2 tx = make_float2(fmaf(xs.x, invx, f2v[k].x),
                                    fmaf(xs.y, invx, f2v[k].y));
            float2 ty = make_float2(fmaf(ys.x, invy, f2v[k].x),
                                    fmaf(ys.y, invy, f2v[k].y));
            ((__half2*)g_thx2)[i] = __float22half2_rn(tx);
            ((__half2*)g_thy2)[i] = __float22half2_rn(ty);
        }
    }
}

// ---------------------------------------------------------------------------
// K3: gather (unchanged from the R12 winner). 8 rows/warp, front-batched.
// Table row half = 64 fp16 = 128B; lanes 0-15 load 8B from THX2[i0],
// lanes 16-31 from THY2[i1]; convert and stream 16B fp32 per lane.
// ---------------------------------------------------------------------------
__global__ void __launch_bounds__(256)
gather_kernel(const int2* __restrict__ pos, float4* __restrict__ out,
              int nrows) {
    int warp = (blockIdx.x * blockDim.x + threadIdx.x) >> 5;
    int lane = threadIdx.x & 31;
    int base = warp * ROWS_PER_WARP;
    if (base >= nrows) return;

    bool use_x = (lane < 16);
    int off = lane & 15;
    const uint2* tab = use_x ? (const uint2*)g_thx2 : (const uint2*)g_thy2;

    int idx[ROWS_PER_WARP];
#pragma unroll
    for (int k = 0; k < ROWS_PER_WARP; k++) {
        int r = base + k;
        int2 p = (r < nrows) ? __ldg(&pos[r]) : make_int2(1, 1);
        int t = use_x ? p.x : p.y;
        idx[k] = (t < 0) ? 1 : t;
    }

    uint2 h[ROWS_PER_WARP];
#pragma unroll
    for (int k = 0; k < ROWS_PER_WARP; k++) {
        h[k] = __ldg(tab + (size_t)idx[k] * 16 + off);   // 16 x 8B per row
    }

#pragma unroll
    for (int k = 0; k < ROWS_PER_WARP; k++) {
        int r = base + k;
        if (r < nrows) {
            float2 a = __half22float2(*(const __half2*)&h[k].x);
            float2 b = __half22float2(*(const __half2*)&h[k].y);
            float4 v = make_float4(a.x, a.y, b.x, b.y);
            __stcs(&out[(size_t)r * 32 + lane], v);
        }
    }
}

extern "C" void kernel_launch(void* const* d_in, const int* in_sizes, int n_in,
                              void* d_out, int out_size) {
    const int*   positions   = (const int*)d_in[0];   // [16,512,32,2] int32
    const float* fixed_table = (const float*)d_in[1]; // [table_len,128]
    const float* table_x     = (const float*)d_in[2];
    const float* table_y     = (const float*)d_in[3];

    int table_elems = in_sizes[1];        // table_len * 128
    int n4_tab      = table_elems / 4;    // float4 count per table
    int nrows       = in_sizes[0] / 2;    // 262144 output rows

    prep_kernel<<<PREPB, 256>>>((const float4*)table_x,
                                (const float4*)table_y,
                                (const float4*)fixed_table, n4_tab);
    scale_kernel<<<SCALEB, 256>>>(n4_tab);
    {
        int threads = 256;  // 8 warps/block, 8 rows/warp
        int nwarps = (nrows + ROWS_PER_WARP - 1) / ROWS_PER_WARP;
        int blocks = (nwarps * 32 + threads - 1) / threads;
        gather_kernel<<<blocks, threads>>>((const int2*)positions,
                                           (float4*)d_out, nrows);
    }
}

// round 17
// speedup vs baseline: 1.0010x; 1.0010x over previous
#include <cuda_runtime.h>
#include <cuda_fp16.h>
#include <float.h>
#include <stdint.h>

#define D2 64
#define MAX_TABLE_LEN 8192
#define MAXB_MAX 528
#define MAXB_BUILD 264
#define ROWS_PER_WARP 8

// Scratch (no allocation allowed in kernel_launch)
// Combined pair-reduced tables in FP16: halves LTS read traffic in the gather
// (the LTS-throughput bottleneck) and shrinks the working set to ~1MB.
__device__ __align__(16) __half g_thx2[MAX_TABLE_LEN * D2];
__device__ __align__(16) __half g_thy2[MAX_TABLE_LEN * D2];
__device__ float g_pmx[MAXB_MAX];
__device__ float g_pmy[MAXB_MAX];
__device__ float g_inv2[2];
__device__ unsigned int g_done = 0;  // fence-counter; last block resets to 0

// ---------------------------------------------------------------------------
// Pass 1: global max of both tables. ONE-SHOT: 528 blocks x 256 thr covers
// n4 (~131K float4s) with a single predicated load per table per thread —
// no loop-carried dependency, whole scan is one DRAM round-trip with MLP
// spread over 135K threads. LAST block to finish (fence-counter, no spin —
// proven across 5 passing rounds) reduces partials -> g_inv2.
// ---------------------------------------------------------------------------
__global__ void __launch_bounds__(256)
max_kernel(const float4* __restrict__ x, const float4* __restrict__ y, int n4) {
    const int tid = threadIdx.x;
    const int i = blockIdx.x * 256 + tid;
    const bool ok = (i < n4);

    float4 a, b;
    if (ok) { a = x[i]; b = y[i]; }

    float mx = -FLT_MAX, my = -FLT_MAX;
    if (ok) {
        mx = fmaxf(fmaxf(a.x, a.y), fmaxf(a.z, a.w));
        my = fmaxf(fmaxf(b.x, b.y), fmaxf(b.z, b.w));
    }

#pragma unroll
    for (int o = 16; o > 0; o >>= 1) {
        mx = fmaxf(mx, __shfl_xor_sync(0xFFFFFFFFu, mx, o));
        my = fmaxf(my, __shfl_xor_sync(0xFFFFFFFFu, my, o));
    }
    __shared__ float smx[8], smy[8];
    __shared__ bool s_last;
    int w = tid >> 5, l = tid & 31;
    if (l == 0) { smx[w] = mx; smy[w] = my; }
    __syncthreads();
    if (tid == 0) {
        for (int k = 1; k < 8; k++) {
            mx = fmaxf(mx, smx[k]);
            my = fmaxf(my, smy[k]);
        }
        g_pmx[blockIdx.x] = mx;
        g_pmy[blockIdx.x] = my;
        __threadfence();
        unsigned int prev = atomicAdd(&g_done, 1u);
        s_last = (prev == MAXB_MAX - 1);
    }
    __syncthreads();

    if (s_last && tid < 32) {
        float fx = -FLT_MAX, fy = -FLT_MAX;
        for (int k = tid; k < MAXB_MAX; k += 32) {
            fx = fmaxf(fx, g_pmx[k]);
            fy = fmaxf(fy, g_pmy[k]);
        }
#pragma unroll
        for (int o = 16; o > 0; o >>= 1) {
            fx = fmaxf(fx, __shfl_xor_sync(0xFFFFFFFFu, fx, o));
            fy = fmaxf(fy, __shfl_xor_sync(0xFFFFFFFFu, fy, o));
        }
        if (tid == 0) {
            g_inv2[0] = 0.1f / fx;
            g_inv2[1] = 0.1f / fy;
            g_done = 0;  // reset for next graph replay
        }
    }
}

// ---------------------------------------------------------------------------
// Pass 2: build COMBINED pair-reduced tables in fp16 (R12 winner, verbatim):
//   THX2[i][j] = half((x[i][2j]+x[i][2j+1]) * invx + (F[i][2j]+F[i][2j+1]))
// 264 blocks x 256 thr, one 2-way-batched pass, loads front-batched.
// x/y are L2-hot from pass 1. Per input float4 -> one half2 (4B) per table.
// ---------------------------------------------------------------------------
__global__ void __launch_bounds__(256)
build_kernel(const float4* __restrict__ x, const float4* __restrict__ y,
             const float4* __restrict__ f, int n4) {
    const int stride = MAXB_BUILD * 256;
    const int i0 = blockIdx.x * 256 + threadIdx.x;
    const int i1 = i0 + stride;
    const bool ok0 = (i0 < n4);
    const bool ok1 = (i1 < n4);

    float4 fa0, xa0, ya0, fa1, xa1, ya1;
    if (ok0) { fa0 = f[i0]; xa0 = x[i0]; ya0 = y[i0]; }
    if (ok1) { fa1 = f[i1]; xa1 = x[i1]; ya1 = y[i1]; }

    const float invx = g_inv2[0];
    const float invy = g_inv2[1];

    if (ok0) {
        float fs0 = fa0.x + fa0.y, fs1 = fa0.z + fa0.w;
        float2 tx = make_float2(fmaf(xa0.x + xa0.y, invx, fs0),
                                fmaf(xa0.z + xa0.w, invx, fs1));
        float2 ty = make_float2(fmaf(ya0.x + ya0.y, invy, fs0),
                                fmaf(ya0.z + ya0.w, invy, fs1));
        ((__half2*)g_thx2)[i0] = __float22half2_rn(tx);
        ((__half2*)g_thy2)[i0] = __float22half2_rn(ty);
    }
    if (ok1) {
        float fs0 = fa1.x + fa1.y, fs1 = fa1.z + fa1.w;
        float2 tx = make_float2(fmaf(xa1.x + xa1.y, invx, fs0),
                                fmaf(xa1.z + xa1.w, invx, fs1));
        float2 ty = make_float2(fmaf(ya1.x + ya1.y, invy, fs0),
                                fmaf(ya1.z + ya1.w, invy, fs1));
        ((__half2*)g_thx2)[i1] = __float22half2_rn(tx);
        ((__half2*)g_thy2)[i1] = __float22half2_rn(ty);
    }
}

// ---------------------------------------------------------------------------
// Pass 3: gather (R12 winner, verbatim). 8 rows/warp, front-batched (MLP=8).
// Table row half = 64 fp16 = 128B; lanes 0-15 load 8B from THX2[i0],
// lanes 16-31 from THY2[i1]; convert and stream 16B fp32 per lane.
// ---------------------------------------------------------------------------
__global__ void __launch_bounds__(256)
gather_kernel(const int2* __restrict__ pos, float4* __restrict__ out,
              int nrows) {
    int warp = (blockIdx.x * blockDim.x + threadIdx.x) >> 5;
    int lane = threadIdx.x & 31;
    int base = warp * ROWS_PER_WARP;
    if (base >= nrows) return;

    bool use_x = (lane < 16);
    int off = lane & 15;
    const uint2* tab = use_x ? (const uint2*)g_thx2 : (const uint2*)g_thy2;

    int idx[ROWS_PER_WARP];
#pragma unroll
    for (int k = 0; k < ROWS_PER_WARP; k++) {
        int r = base + k;
        int2 p = (r < nrows) ? __ldg(&pos[r]) : make_int2(1, 1);
        int t = use_x ? p.x : p.y;
        idx[k] = (t < 0) ? 1 : t;
    }

    uint2 h[ROWS_PER_WARP];
#pragma unroll
    for (int k = 0; k < ROWS_PER_WARP; k++) {
        h[k] = __ldg(tab + (size_t)idx[k] * 16 + off);   // 16 x 8B per row
    }

#pragma unroll
    for (int k = 0; k < ROWS_PER_WARP; k++) {
        int r = base + k;
        if (r < nrows) {
            float2 a = __half22float2(*(const __half2*)&h[k].x);
            float2 b = __half22float2(*(const __half2*)&h[k].y);
            float4 v = make_float4(a.x, a.y, b.x, b.y);
            __stcs(&out[(size_t)r * 32 + lane], v);
        }
    }
}

extern "C" void kernel_launch(void* const* d_in, const int* in_sizes, int n_in,
                              void* d_out, int out_size) {
    const int*   positions   = (const int*)d_in[0];   // [16,512,32,2] int32
    const float* fixed_table = (const float*)d_in[1]; // [table_len,128]
    const float* table_x     = (const float*)d_in[2];
    const float* table_y     = (const float*)d_in[3];

    int table_elems = in_sizes[1];        // table_len * 128
    int n4_tab      = table_elems / 4;    // float4 count per table
    int nrows       = in_sizes[0] / 2;    // 262144 output rows

    max_kernel<<<MAXB_MAX, 256>>>((const float4*)table_x,
                                  (const float4*)table_y, n4_tab);
    build_kernel<<<MAXB_BUILD, 256>>>((const float4*)table_x,
                                      (const float4*)table_y,
                                      (const float4*)fixed_table, n4_tab);
    {
        int threads = 256;  // 8 warps/block, 8 rows/warp
        int nwarps = (nrows + ROWS_PER_WARP - 1) / ROWS_PER_WARP;
        int blocks = (nwarps * 32 + threads - 1) / threads;
        gather_kernel<<<blocks, threads>>>((const int2*)positions,
                                           (float4*)d_out, nrows);
    }
}